// round 1
// baseline (speedup 1.0000x reference)
#include <cuda_runtime.h>

#define D 128
#define MAXN 100000
#define MAXE 500000
#define MAXR 237

// ---- scratch (device globals; no allocation allowed) ----
__device__ float g_Mcat[D * 256];            // fused W_ent@[W2a|W2b], [128][256]
__device__ float g_bias[256];                // b_ent@W2a | b_ent@W2b
__device__ float g_pc[MAXR * D];             // per-relation term incl. b_ent2
__device__ float g_pab[(size_t)MAXN * 256];  // per-node pa|pb (102.4 MB)
__device__ int   g_cnt[MAXN];
__device__ int   g_rowptr[MAXN + 1];
__device__ int   g_cursor[MAXN];
__device__ int   g_edst[MAXE];
__device__ int   g_erel[MAXE];

// ---- f32x2 packed-FMA helpers (sm_103a FFMA2 path) ----
__device__ __forceinline__ unsigned long long pk2(float lo, float hi) {
    unsigned long long r;
    asm("mov.b64 %0, {%1, %2};" : "=l"(r) : "f"(lo), "f"(hi));
    return r;
}
__device__ __forceinline__ void upk2(unsigned long long v, float& lo, float& hi) {
    asm("mov.b64 {%0, %1}, %2;" : "=f"(lo), "=f"(hi) : "l"(v));
}
__device__ __forceinline__ unsigned long long fma2(unsigned long long a,
                                                   unsigned long long b,
                                                   unsigned long long c) {
    unsigned long long d;
    asm("fma.rn.f32x2 %0, %1, %2, %3;" : "=l"(d) : "l"(a), "l"(b), "l"(c));
    return d;
}

// ---- kernel 1: fuse weights, per-relation term, bias; zero histogram ----
__global__ void prep_kernel(const float* __restrict__ W_ent,
                            const float* __restrict__ b_ent,
                            const float* __restrict__ W_rel,
                            const float* __restrict__ b_rel,
                            const float* __restrict__ W_ent2,
                            const float* __restrict__ b_ent2,
                            const float* __restrict__ rel_embed,
                            int n_rels, int n_nodes) {
    int b = blockIdx.x, t = threadIdx.x;
    if (b < D) {
        // row b of Mcat = W_ent[b,:] @ [W2a | W2b]
        __shared__ float wrow[D];
        wrow[t] = W_ent[b * D + t];
        __syncthreads();
        float s0 = 0.f, s1 = 0.f;
#pragma unroll 4
        for (int k = 0; k < D; k++) {
            float w = wrow[k];
            s0 += w * W_ent2[k * D + t];
            s1 += w * W_ent2[(D + k) * D + t];
        }
        g_Mcat[b * 256 + t]     = s0;
        g_Mcat[b * 256 + D + t] = s1;
    } else if (b < D + n_rels) {
        int r = b - D;
        __shared__ float rp[D];
        float s = b_rel[t];
#pragma unroll 4
        for (int i = 0; i < D; i++) s += rel_embed[r * D + i] * W_rel[i * D + t];
        rp[t] = s;
        __syncthreads();
        float o = b_ent2[t];
#pragma unroll 4
        for (int k = 0; k < D; k++) o += rp[k] * W_ent2[(2 * D + k) * D + t];
        g_pc[r * D + t] = o;
    } else {
        float s0 = 0.f, s1 = 0.f;
        for (int k = 0; k < D; k++) {
            float bv = b_ent[k];
            s0 += bv * W_ent2[k * D + t];
            s1 += bv * W_ent2[(D + k) * D + t];
        }
        g_bias[t]     = s0;
        g_bias[D + t] = s1;
    }
    // every block helps zero the histogram
    for (int i = b * blockDim.x + t; i < n_nodes; i += gridDim.x * blockDim.x)
        g_cnt[i] = 0;
}

// ---- kernel 2: out-degree histogram ----
__global__ void hist_kernel(const int* __restrict__ trip, int E) {
    for (int e = blockIdx.x * blockDim.x + threadIdx.x; e < E;
         e += gridDim.x * blockDim.x)
        atomicAdd(&g_cnt[trip[e * 3]], 1);
}

// ---- kernel 3: single-block exclusive scan -> rowptr + cursor ----
__global__ void scan_kernel(int n_nodes) {
    __shared__ int sm[1024];
    int t = threadIdx.x;
    int CH = (n_nodes + 1023) >> 10;
    int lo = t * CH;
    int hi = min(lo + CH, n_nodes);
    int s = 0;
    for (int i = lo; i < hi; i++) s += g_cnt[i];
    sm[t] = s;
    __syncthreads();
    for (int off = 1; off < 1024; off <<= 1) {
        int v = (t >= off) ? sm[t - off] : 0;
        __syncthreads();
        sm[t] += v;
        __syncthreads();
    }
    int run = sm[t] - s;  // exclusive prefix
    for (int i = lo; i < hi; i++) {
        g_rowptr[i] = run;
        g_cursor[i] = run;
        run += g_cnt[i];
    }
    if (t == 1023) g_rowptr[n_nodes] = sm[1023];
}

// ---- kernel 4: scatter edges into CSR (dst, rel sorted by src) ----
__global__ void scatter_kernel(const int* __restrict__ trip, int E) {
    for (int e = blockIdx.x * blockDim.x + threadIdx.x; e < E;
         e += gridDim.x * blockDim.x) {
        int src = trip[e * 3];
        int dst = trip[e * 3 + 1];
        int rel = trip[e * 3 + 2];
        int p = atomicAdd(&g_cursor[src], 1);
        g_edst[p] = dst;
        g_erel[p] = rel;
    }
}

// ---- kernel 5: node projection GEMM: g_pab = ent_embed @ Mcat + bias ----
// Block: 64 rows x 128 cols (blockIdx.y selects pa/pb half), 256 threads,
// thread tile 8x4, accumulation in packed f32x2 (FFMA2).
__global__ __launch_bounds__(256, 2) void gemm_kernel(const float* __restrict__ ent,
                                                      int N) {
    extern __shared__ float smem[];
    float* As = smem;            // [128][64] k-major (transposed A tile), 32 KB
    float* Bs = smem + D * 64;   // [128][128], 64 KB
    const int tid = threadIdx.x;
    const int rb = blockIdx.x * 64;
    const int y = blockIdx.y;

    // load Bs (half of Mcat)
    {
        float4* Bs4 = (float4*)Bs;
        const float4* M4 = (const float4*)g_Mcat;
#pragma unroll
        for (int j = 0; j < 16; j++) {
            int f = j * 256 + tid;         // 0..4095 float4s
            int k = f >> 5, jq = f & 31;
            Bs4[f] = M4[k * 64 + y * 32 + jq];
        }
    }
    // load A tile transposed: As[k][row]
    {
        const float4* E4 = (const float4*)ent;
#pragma unroll
        for (int j = 0; j < 8; j++) {
            int f = j * 256 + tid;         // 0..2047 float4s over 64x32
            int r = f >> 5, kq = f & 31;
            int row = rb + r;
            if (row >= N) row = N - 1;     // clamped pad read; stores guarded
            float4 g = E4[(size_t)row * 32 + kq];
            float* dp = As + (kq * 4) * 64 + r;
            dp[0] = g.x; dp[64] = g.y; dp[128] = g.z; dp[192] = g.w;
        }
    }
    __syncthreads();

    const int tc = tid & 31, tr = tid >> 5;
    unsigned long long acc[4][4];
    {
        const float* bi = g_bias + y * D + tc * 4;
#pragma unroll
        for (int c = 0; c < 4; c++) {
            float bv = bi[c];
            unsigned long long p = pk2(bv, bv);
#pragma unroll
            for (int rp = 0; rp < 4; rp++) acc[rp][c] = p;
        }
    }
    const float4* As4 = (const float4*)As;
    const float4* B4 = (const float4*)Bs;
#pragma unroll 4
    for (int k = 0; k < D; k++) {
        float4 a0 = As4[k * 16 + tr * 2];
        float4 a1 = As4[k * 16 + tr * 2 + 1];
        float4 bv = B4[k * 32 + tc];
        unsigned long long ap0 = pk2(a0.x, a0.y);
        unsigned long long ap1 = pk2(a0.z, a0.w);
        unsigned long long ap2 = pk2(a1.x, a1.y);
        unsigned long long ap3 = pk2(a1.z, a1.w);
        unsigned long long bp0 = pk2(bv.x, bv.x);
        unsigned long long bp1 = pk2(bv.y, bv.y);
        unsigned long long bp2 = pk2(bv.z, bv.z);
        unsigned long long bp3 = pk2(bv.w, bv.w);
        acc[0][0] = fma2(ap0, bp0, acc[0][0]);
        acc[0][1] = fma2(ap0, bp1, acc[0][1]);
        acc[0][2] = fma2(ap0, bp2, acc[0][2]);
        acc[0][3] = fma2(ap0, bp3, acc[0][3]);
        acc[1][0] = fma2(ap1, bp0, acc[1][0]);
        acc[1][1] = fma2(ap1, bp1, acc[1][1]);
        acc[1][2] = fma2(ap1, bp2, acc[1][2]);
        acc[1][3] = fma2(ap1, bp3, acc[1][3]);
        acc[2][0] = fma2(ap2, bp0, acc[2][0]);
        acc[2][1] = fma2(ap2, bp1, acc[2][1]);
        acc[2][2] = fma2(ap2, bp2, acc[2][2]);
        acc[2][3] = fma2(ap2, bp3, acc[2][3]);
        acc[3][0] = fma2(ap3, bp0, acc[3][0]);
        acc[3][1] = fma2(ap3, bp1, acc[3][1]);
        acc[3][2] = fma2(ap3, bp2, acc[3][2]);
        acc[3][3] = fma2(ap3, bp3, acc[3][3]);
    }
    float4* out4 = (float4*)g_pab;
#pragma unroll
    for (int rp = 0; rp < 4; rp++) {
        float4 lo4, hi4;
        upk2(acc[rp][0], lo4.x, hi4.x);
        upk2(acc[rp][1], lo4.y, hi4.y);
        upk2(acc[rp][2], lo4.z, hi4.z);
        upk2(acc[rp][3], lo4.w, hi4.w);
        int r0 = rb + tr * 8 + rp * 2;
        if (r0 < N)     out4[(size_t)r0 * 64 + y * 32 + tc] = lo4;
        if (r0 + 1 < N) out4[(size_t)(r0 + 1) * 64 + y * 32 + tc] = hi4;
    }
}

// ---- kernel 6: warp-per-node aggregation (no float atomics) ----
__global__ void agg_kernel(const float* __restrict__ aw,
                           const float* __restrict__ abp,
                           float* __restrict__ h, int N) {
    int gw = (blockIdx.x * blockDim.x + threadIdx.x) >> 5;
    int lane = threadIdx.x & 31;
    if (gw >= N) return;
    const float4* pab4 = (const float4*)g_pab;
    const float4* pc4 = (const float4*)g_pc;
    float4 pa = pab4[(size_t)gw * 64 + lane];       // pa cols (first 128)
    float4 a4 = ((const float4*)aw)[lane];
    float ab = abp[0];
    int beg = g_rowptr[gw], end = g_rowptr[gw + 1];
    float4 acc = {0.f, 0.f, 0.f, 0.f};
    float bsum = 0.f;
    for (int e = beg; e < end; e++) {
        int dst = g_edst[e];
        int rel = g_erel[e];
        float4 pb = pab4[(size_t)dst * 64 + 32 + lane];  // pb half
        float4 pcv = pc4[rel * 32 + lane];
        float4 c;
        c.x = pa.x + pb.x + pcv.x;
        c.y = pa.y + pb.y + pcv.y;
        c.z = pa.z + pb.z + pcv.z;
        c.w = pa.w + pb.w + pcv.w;
        float s = c.x * a4.x + c.y * a4.y + c.z * a4.z + c.w * a4.w;
        s += __shfl_xor_sync(0xffffffffu, s, 16);
        s += __shfl_xor_sync(0xffffffffu, s, 8);
        s += __shfl_xor_sync(0xffffffffu, s, 4);
        s += __shfl_xor_sync(0xffffffffu, s, 2);
        s += __shfl_xor_sync(0xffffffffu, s, 1);
        s += ab;
        s = s > 0.f ? s : 0.01f * s;   // leaky_relu(0.01)
        float b = __expf(s);
        bsum += b;
        acc.x += b * c.x;
        acc.y += b * c.y;
        acc.z += b * c.z;
        acc.w += b * c.w;
    }
    float4 o = {0.f, 0.f, 0.f, 0.f};
    if (end > beg) {
        float inv = 1.f / bsum;
        o.x = acc.x * inv; o.y = acc.y * inv;
        o.z = acc.z * inv; o.w = acc.w * inv;
    }
    ((float4*)h)[(size_t)gw * 32 + lane] = o;
}

extern "C" void kernel_launch(void* const* d_in, const int* in_sizes, int n_in,
                              void* d_out, int out_size) {
    const int*   trip    = (const int*)d_in[0];
    const float* ent     = (const float*)d_in[1];
    const float* rel     = (const float*)d_in[2];
    const float* W_ent   = (const float*)d_in[3];
    const float* b_ent   = (const float*)d_in[4];
    const float* W_rel   = (const float*)d_in[5];
    const float* b_rel   = (const float*)d_in[6];
    const float* W_ent2  = (const float*)d_in[7];
    const float* b_ent2  = (const float*)d_in[8];
    const float* a_w     = (const float*)d_in[9];
    const float* a_b     = (const float*)d_in[10];

    int E = in_sizes[0] / 3;
    int N = in_sizes[1] / D;
    int R = in_sizes[2] / D;

    cudaFuncSetAttribute(gemm_kernel, cudaFuncAttributeMaxDynamicSharedMemorySize,
                         98304);

    prep_kernel<<<D + R + 1, D>>>(W_ent, b_ent, W_rel, b_rel, W_ent2, b_ent2,
                                  rel, R, N);
    hist_kernel<<<1024, 256>>>(trip, E);
    scan_kernel<<<1, 1024>>>(N);
    scatter_kernel<<<1024, 256>>>(trip, E);
    gemm_kernel<<<dim3((N + 63) / 64, 2), 256, 98304>>>(ent, N);
    agg_kernel<<<(N * 32 + 255) / 256, 256>>>(a_w, a_b, (float*)d_out, N);
}

// round 2
// speedup vs baseline: 1.5408x; 1.5408x over previous
#include <cuda_runtime.h>
#include <cuda_fp16.h>

#define D 128
#define MAXN 100000
#define MAXE 500000
#define MAXR 237
#define SCB  512                      // scan chunk
#define NBLK ((MAXN + SCB - 1) / SCB) // 196

// ---- scratch (device globals; no allocation allowed) ----
__device__ float  g_Mcat[D * 256];           // fused W_ent@[W2a|W2b]
__device__ float  g_bias[256];
__device__ float  g_pc[MAXR * D];            // per-relation term incl. b_ent2
__device__ float  g_qc[MAXR];                // pc . a_w
__device__ float  g_pa[(size_t)MAXN * D];    // fp32, 51.2 MB
__device__ __half g_pbh[(size_t)MAXN * D];   // fp16, 25.6 MB (gathered)
__device__ float  g_qa[MAXN];
__device__ float  g_qb[MAXN];
__device__ float  g_bw[MAXE];                // per-edge weight b_e
__device__ int    g_cnt[MAXN];
__device__ int    g_rowptr[MAXN + 1];
__device__ int    g_cursor[MAXN];
__device__ int    g_edst[MAXE];
__device__ int    g_erel[MAXE];
__device__ int    g_bsum[NBLK];
__device__ int    g_boff[NBLK];

// ---- f32x2 packed-FMA helpers ----
__device__ __forceinline__ unsigned long long pk2(float lo, float hi) {
    unsigned long long r;
    asm("mov.b64 %0, {%1, %2};" : "=l"(r) : "f"(lo), "f"(hi));
    return r;
}
__device__ __forceinline__ void upk2(unsigned long long v, float& lo, float& hi) {
    asm("mov.b64 {%0, %1}, %2;" : "=f"(lo), "=f"(hi) : "l"(v));
}
__device__ __forceinline__ unsigned long long fma2(unsigned long long a,
                                                   unsigned long long b,
                                                   unsigned long long c) {
    unsigned long long d;
    asm("fma.rn.f32x2 %0, %1, %2, %3;" : "=l"(d) : "l"(a), "l"(b), "l"(c));
    return d;
}

// ---- kernel 1: weight fusion, per-relation term + qc, bias; zero histogram ----
__global__ void prep_kernel(const float* __restrict__ W_ent,
                            const float* __restrict__ b_ent,
                            const float* __restrict__ W_rel,
                            const float* __restrict__ b_rel,
                            const float* __restrict__ W_ent2,
                            const float* __restrict__ b_ent2,
                            const float* __restrict__ rel_embed,
                            const float* __restrict__ a_w,
                            int n_rels, int n_nodes) {
    int b = blockIdx.x, t = threadIdx.x;
    if (b < D) {
        __shared__ float wrow[D];
        wrow[t] = W_ent[b * D + t];
        __syncthreads();
        float s0 = 0.f, s1 = 0.f;
#pragma unroll 4
        for (int k = 0; k < D; k++) {
            float w = wrow[k];
            s0 += w * W_ent2[k * D + t];
            s1 += w * W_ent2[(D + k) * D + t];
        }
        g_Mcat[b * 256 + t]     = s0;
        g_Mcat[b * 256 + D + t] = s1;
    } else if (b < D + n_rels) {
        int r = b - D;
        __shared__ float rp[D];
        __shared__ float red[D];
        float s = b_rel[t];
#pragma unroll 4
        for (int i = 0; i < D; i++) s += rel_embed[r * D + i] * W_rel[i * D + t];
        rp[t] = s;
        __syncthreads();
        float o = b_ent2[t];
#pragma unroll 4
        for (int k = 0; k < D; k++) o += rp[k] * W_ent2[(2 * D + k) * D + t];
        g_pc[r * D + t] = o;
        red[t] = o * a_w[t];
        __syncthreads();
        for (int off = 64; off > 0; off >>= 1) {
            if (t < off) red[t] += red[t + off];
            __syncthreads();
        }
        if (t == 0) g_qc[r] = red[0];
    } else {
        float s0 = 0.f, s1 = 0.f;
        for (int k = 0; k < D; k++) {
            float bv = b_ent[k];
            s0 += bv * W_ent2[k * D + t];
            s1 += bv * W_ent2[(D + k) * D + t];
        }
        g_bias[t]     = s0;
        g_bias[D + t] = s1;
    }
    for (int i = b * blockDim.x + t; i < n_nodes; i += gridDim.x * blockDim.x)
        g_cnt[i] = 0;
}

// ---- kernel 2: out-degree histogram ----
__global__ void hist_kernel(const int* __restrict__ trip, int E) {
    for (int e = blockIdx.x * blockDim.x + threadIdx.x; e < E;
         e += gridDim.x * blockDim.x)
        atomicAdd(&g_cnt[trip[e * 3]], 1);
}

// ---- kernels 3a/3b/3c: multi-block exclusive scan ----
__global__ void scan1_kernel(int N) {
    __shared__ int sm[SCB];
    int t = threadIdx.x;
    int i = blockIdx.x * SCB + t;
    sm[t] = (i < N) ? g_cnt[i] : 0;
    __syncthreads();
    for (int off = SCB / 2; off > 0; off >>= 1) {
        if (t < off) sm[t] += sm[t + off];
        __syncthreads();
    }
    if (t == 0) g_bsum[blockIdx.x] = sm[0];
}
__global__ void scan2_kernel(int nblk, int N) {
    __shared__ int sm[256];
    int t = threadIdx.x;
    int v = (t < nblk) ? g_bsum[t] : 0;
    sm[t] = v;
    __syncthreads();
    for (int off = 1; off < 256; off <<= 1) {
        int u = (t >= off) ? sm[t - off] : 0;
        __syncthreads();
        sm[t] += u;
        __syncthreads();
    }
    if (t < nblk) g_boff[t] = sm[t] - v;
    if (t == 255) g_rowptr[N] = sm[255];
}
__global__ void scan3_kernel(int N) {
    __shared__ int sm[SCB];
    int t = threadIdx.x;
    int i = blockIdx.x * SCB + t;
    int v = (i < N) ? g_cnt[i] : 0;
    sm[t] = v;
    __syncthreads();
    for (int off = 1; off < SCB; off <<= 1) {
        int u = (t >= off) ? sm[t - off] : 0;
        __syncthreads();
        sm[t] += u;
        __syncthreads();
    }
    if (i < N) {
        int val = g_boff[blockIdx.x] + sm[t] - v;
        g_rowptr[i] = val;
        g_cursor[i] = val;
    }
}

// ---- kernel 4: scatter edges into CSR + compute edge weight b_e ----
__global__ void scatter_b_kernel(const int* __restrict__ trip,
                                 const float* __restrict__ abp, int E) {
    float ab = abp[0];
    for (int e = blockIdx.x * blockDim.x + threadIdx.x; e < E;
         e += gridDim.x * blockDim.x) {
        int src = trip[e * 3];
        int dst = trip[e * 3 + 1];
        int rel = trip[e * 3 + 2];
        int p = atomicAdd(&g_cursor[src], 1);
        g_edst[p] = dst;
        g_erel[p] = rel;
        float s = g_qa[src] + g_qb[dst] + g_qc[rel] + ab;
        s = s > 0.f ? s : 0.01f * s;   // leaky_relu(0.01)
        g_bw[p] = __expf(s);
    }
}

// ---- kernel 5: node GEMM -> pa (fp32) / pb (fp16) + qa/qb epilogue ----
__global__ __launch_bounds__(256, 2) void gemm_kernel(const float* __restrict__ ent,
                                                      const float* __restrict__ a_w,
                                                      int N) {
    extern __shared__ float smem[];
    float* As = smem;            // [128][64] k-major, 32 KB
    float* Bs = smem + D * 64;   // [128][128], 64 KB
    const int tid = threadIdx.x;
    const int rb = blockIdx.x * 64;
    const int y = blockIdx.y;

    {
        float4* Bs4 = (float4*)Bs;
        const float4* M4 = (const float4*)g_Mcat;
#pragma unroll
        for (int j = 0; j < 16; j++) {
            int f = j * 256 + tid;
            int k = f >> 5, jq = f & 31;
            Bs4[f] = M4[k * 64 + y * 32 + jq];
        }
    }
    {
        const float4* E4 = (const float4*)ent;
#pragma unroll
        for (int j = 0; j < 8; j++) {
            int f = j * 256 + tid;
            int r = f >> 5, kq = f & 31;
            int row = rb + r;
            if (row >= N) row = N - 1;
            float4 g = E4[(size_t)row * 32 + kq];
            float* dp = As + (kq * 4) * 64 + r;
            dp[0] = g.x; dp[64] = g.y; dp[128] = g.z; dp[192] = g.w;
        }
    }
    __syncthreads();

    const int tc = tid & 31, tr = tid >> 5;
    unsigned long long acc[4][4];
    {
        const float* bi = g_bias + y * D + tc * 4;
#pragma unroll
        for (int c = 0; c < 4; c++) {
            float bv = bi[c];
            unsigned long long p = pk2(bv, bv);
#pragma unroll
            for (int rp = 0; rp < 4; rp++) acc[rp][c] = p;
        }
    }
    const float4* As4 = (const float4*)As;
    const float4* B4 = (const float4*)Bs;
#pragma unroll 4
    for (int k = 0; k < D; k++) {
        float4 a0 = As4[k * 16 + tr * 2];
        float4 a1 = As4[k * 16 + tr * 2 + 1];
        float4 bv = B4[k * 32 + tc];
        unsigned long long ap0 = pk2(a0.x, a0.y);
        unsigned long long ap1 = pk2(a0.z, a0.w);
        unsigned long long ap2 = pk2(a1.x, a1.y);
        unsigned long long ap3 = pk2(a1.z, a1.w);
        unsigned long long bp0 = pk2(bv.x, bv.x);
        unsigned long long bp1 = pk2(bv.y, bv.y);
        unsigned long long bp2 = pk2(bv.z, bv.z);
        unsigned long long bp3 = pk2(bv.w, bv.w);
        acc[0][0] = fma2(ap0, bp0, acc[0][0]);
        acc[0][1] = fma2(ap0, bp1, acc[0][1]);
        acc[0][2] = fma2(ap0, bp2, acc[0][2]);
        acc[0][3] = fma2(ap0, bp3, acc[0][3]);
        acc[1][0] = fma2(ap1, bp0, acc[1][0]);
        acc[1][1] = fma2(ap1, bp1, acc[1][1]);
        acc[1][2] = fma2(ap1, bp2, acc[1][2]);
        acc[1][3] = fma2(ap1, bp3, acc[1][3]);
        acc[2][0] = fma2(ap2, bp0, acc[2][0]);
        acc[2][1] = fma2(ap2, bp1, acc[2][1]);
        acc[2][2] = fma2(ap2, bp2, acc[2][2]);
        acc[2][3] = fma2(ap2, bp3, acc[2][3]);
        acc[3][0] = fma2(ap3, bp0, acc[3][0]);
        acc[3][1] = fma2(ap3, bp1, acc[3][1]);
        acc[3][2] = fma2(ap3, bp2, acc[3][2]);
        acc[3][3] = fma2(ap3, bp3, acc[3][3]);
    }

    // epilogue: store pa (fp32) or pb (fp16), plus per-row dot with a_w
    const float4 aw4 = ((const float4*)a_w)[tc];
    float p[8];
#pragma unroll
    for (int rp = 0; rp < 4; rp++) {
        float4 lo4, hi4;
        upk2(acc[rp][0], lo4.x, hi4.x);
        upk2(acc[rp][1], lo4.y, hi4.y);
        upk2(acc[rp][2], lo4.z, hi4.z);
        upk2(acc[rp][3], lo4.w, hi4.w);
        p[rp * 2]     = lo4.x * aw4.x + lo4.y * aw4.y + lo4.z * aw4.z + lo4.w * aw4.w;
        p[rp * 2 + 1] = hi4.x * aw4.x + hi4.y * aw4.y + hi4.z * aw4.z + hi4.w * aw4.w;
        int r0 = rb + tr * 8 + rp * 2;
        if (y == 0) {
            float4* out4 = (float4*)g_pa;
            if (r0 < N)     out4[(size_t)r0 * 32 + tc] = lo4;
            if (r0 + 1 < N) out4[(size_t)(r0 + 1) * 32 + tc] = hi4;
        } else {
            uint2* outh = (uint2*)g_pbh;
            __half2 a0h = __floats2half2_rn(lo4.x, lo4.y);
            __half2 a1h = __floats2half2_rn(lo4.z, lo4.w);
            __half2 b0h = __floats2half2_rn(hi4.x, hi4.y);
            __half2 b1h = __floats2half2_rn(hi4.z, hi4.w);
            uint2 ulo, uhi;
            ulo.x = *(unsigned int*)&a0h; ulo.y = *(unsigned int*)&a1h;
            uhi.x = *(unsigned int*)&b0h; uhi.y = *(unsigned int*)&b1h;
            if (r0 < N)     outh[(size_t)r0 * 32 + tc] = ulo;
            if (r0 + 1 < N) outh[(size_t)(r0 + 1) * 32 + tc] = uhi;
        }
    }
#pragma unroll
    for (int off = 16; off > 0; off >>= 1) {
#pragma unroll
        for (int i = 0; i < 8; i++)
            p[i] += __shfl_xor_sync(0xffffffffu, p[i], off);
    }
    if (tc == 0) {
        float* q = (y == 0) ? g_qa : g_qb;
#pragma unroll
        for (int i = 0; i < 8; i++) {
            int r = rb + tr * 8 + i;
            if (r < N) q[r] = p[i];
        }
    }
}

// ---- kernel 6: warp-per-node aggregation ----
__global__ void agg_kernel(float* __restrict__ h, int N) {
    int gw = (blockIdx.x * blockDim.x + threadIdx.x) >> 5;
    int lane = threadIdx.x & 31;
    if (gw >= N) return;
    int beg = g_rowptr[gw], end = g_rowptr[gw + 1];
    if (beg == end) {
        float4 z = {0.f, 0.f, 0.f, 0.f};
        ((float4*)h)[(size_t)gw * 32 + lane] = z;
        return;
    }
    const uint2* pbh2 = (const uint2*)g_pbh;
    const float4* pc4 = (const float4*)g_pc;
    float4 acc = {0.f, 0.f, 0.f, 0.f};
    float bsum = 0.f;
    for (int e = beg; e < end; e++) {
        float bj = g_bw[e];
        int dj = g_edst[e];
        int rj = g_erel[e];
        uint2 u = pbh2[(size_t)dj * 32 + lane];
        __half2 h0 = *(__half2*)&u.x;
        __half2 h1 = *(__half2*)&u.y;
        float2 f0 = __half22float2(h0);
        float2 f1 = __half22float2(h1);
        float4 pcv = pc4[rj * 32 + lane];
        bsum += bj;
        acc.x += bj * (f0.x + pcv.x);
        acc.y += bj * (f0.y + pcv.y);
        acc.z += bj * (f1.x + pcv.z);
        acc.w += bj * (f1.y + pcv.w);
    }
    float4 pa = ((const float4*)g_pa)[(size_t)gw * 32 + lane];
    float inv = 1.f / bsum;
    float4 o;
    o.x = pa.x + acc.x * inv;
    o.y = pa.y + acc.y * inv;
    o.z = pa.z + acc.z * inv;
    o.w = pa.w + acc.w * inv;
    ((float4*)h)[(size_t)gw * 32 + lane] = o;
}

extern "C" void kernel_launch(void* const* d_in, const int* in_sizes, int n_in,
                              void* d_out, int out_size) {
    const int*   trip    = (const int*)d_in[0];
    const float* ent     = (const float*)d_in[1];
    const float* rel     = (const float*)d_in[2];
    const float* W_ent   = (const float*)d_in[3];
    const float* b_ent   = (const float*)d_in[4];
    const float* W_rel   = (const float*)d_in[5];
    const float* b_rel   = (const float*)d_in[6];
    const float* W_ent2  = (const float*)d_in[7];
    const float* b_ent2  = (const float*)d_in[8];
    const float* a_w     = (const float*)d_in[9];
    const float* a_b     = (const float*)d_in[10];

    int E = in_sizes[0] / 3;
    int N = in_sizes[1] / D;
    int R = in_sizes[2] / D;
    int nblk = (N + SCB - 1) / SCB;

    cudaFuncSetAttribute(gemm_kernel, cudaFuncAttributeMaxDynamicSharedMemorySize,
                         98304);

    prep_kernel<<<D + R + 1, D>>>(W_ent, b_ent, W_rel, b_rel, W_ent2, b_ent2,
                                  rel, a_w, R, N);
    gemm_kernel<<<dim3((N + 63) / 64, 2), 256, 98304>>>(ent, a_w, N);
    hist_kernel<<<1024, 256>>>(trip, E);
    scan1_kernel<<<nblk, SCB>>>(N);
    scan2_kernel<<<1, 256>>>(nblk, N);
    scan3_kernel<<<nblk, SCB>>>(N);
    scatter_b_kernel<<<1024, 256>>>(trip, a_b, E);
    agg_kernel<<<(N * 32 + 255) / 256, 256>>>((float*)d_out, N);
}